// round 1
// baseline (speedup 1.0000x reference)
#include <cuda_runtime.h>
#include <math.h>

typedef unsigned long long ull;

#define NB 16
#define HP 256
#define HW 65536
#define NTOT (NB*HW)

// ---------------- static device scratch ----------------
__device__ float g_h1[(size_t)NB*32*HW];   // 128MB hidden
__device__ float g_h2[(size_t)NB*32*HW];   // 128MB hidden / g-features
__device__ float g_h3[(size_t)NB*32*HW];   // 128MB s-features
__device__ float g_wv[NTOT];               // vertical edge weights (row i <-> i+1), row 255 = 0
__device__ float g_wh[NTOT];               // horizontal edge weights (col j <-> j+1), col 255 = 0
__device__ float g_r[NTOT];
__device__ float g_p[NTOT];
__device__ float g_Ap[NTOT];
__device__ float g_scal[256];              // [0..100]=rs_k, [101..200]=pAp_k, [240]=<b,b>, [241]=atol2

// ---------------- f32x2 helpers (full-rate fp32 FMA on sm_103a) ----------------
__device__ __forceinline__ ull pack2(float a, float b){ ull r; asm("mov.b64 %0, {%1, %2};" : "=l"(r) : "f"(a), "f"(b)); return r; }
__device__ __forceinline__ void ffma2(ull& d, ull a, ull b){ asm("fma.rn.f32x2 %0, %1, %2, %0;" : "+l"(d) : "l"(a), "l"(b)); }
__device__ __forceinline__ float2 unpack2(ull v){ float2 f; asm("mov.b64 {%0, %1}, %2;" : "=f"(f.x), "=f"(f.y) : "l"(v)); return f; }

__global__ void zero_scal_kernel(){ g_scal[threadIdx.x] = 0.f; }

// ---------------- direct 3x3 SAME conv, NCHW, f32 ----------------
// Tile: 16 wide x 32 tall, 256 threads, each thread computes 2 vertically-adjacent pixels
// for all COUT channels. Weights transposed in smem to [(ci*9+tap)*COUT + co] so channel
// pairs are contiguous 8B -> LDS.64 + fma.rn.f32x2.
template<int CINA,int CINB,int COUT,bool RELU>
__global__ void __launch_bounds__(256) conv3x3_kernel(
    const float* __restrict__ inA, const float* __restrict__ inB,
    const float* __restrict__ W, const float* __restrict__ bias,
    float* __restrict__ out)
{
  constexpr int CIN = CINA + CINB;
  extern __shared__ float smem[];
  float* s_in = smem;              // CIN * 34 * 18
  float* s_w  = smem + CIN*612;    // CIN*9*COUT
  const int b  = blockIdx.z;
  const int tx0 = blockIdx.x*16, ty0 = blockIdx.y*32;

  // load + transpose weights (W is OIHW: [co][ci][ky][kx])
  for (int idx = threadIdx.x; idx < COUT*CIN*9; idx += 256){
    int co = idx/(CIN*9); int rem2 = idx - co*CIN*9;
    s_w[rem2*COUT + co] = W[idx];
  }
  // load input tile with 1-px halo, zero padded (SAME)
  for (int ci = 0; ci < CIN; ++ci){
    const float* src = (ci < CINA) ? (inA + ((size_t)b*CINA + ci)*HW)
                                   : (inB + ((size_t)b*CINB + (ci-CINA))*HW);
    for (int idx = threadIdx.x; idx < 612; idx += 256){
      int yy = idx/18, xx = idx - yy*18;
      int gy = ty0+yy-1, gx = tx0+xx-1;
      float v = 0.f;
      if (gy >= 0 && gy < HP && gx >= 0 && gx < HP) v = src[gy*HP+gx];
      s_in[ci*612 + idx] = v;
    }
  }
  __syncthreads();

  const int px  = threadIdx.x & 15;
  const int py2 = (threadIdx.x >> 4) * 2;
  const int gx  = tx0 + px, gy0 = ty0 + py2;

  if constexpr (COUT >= 2){
    constexpr int NPK = COUT/2;
    ull acc0[NPK], acc1[NPK];
    #pragma unroll
    for (int kq = 0; kq < NPK; kq++){
      ull bz = pack2(__ldg(&bias[2*kq]), __ldg(&bias[2*kq+1]));
      acc0[kq] = bz; acc1[kq] = bz;
    }
    #pragma unroll 1
    for (int ci = 0; ci < CIN; ci++){
      const float* sb = s_in + ci*612 + py2*18 + px;
      float v[4][3];
      #pragma unroll
      for (int dy = 0; dy < 4; dy++)
        #pragma unroll
        for (int dx = 0; dx < 3; dx++) v[dy][dx] = sb[dy*18 + dx];
      #pragma unroll
      for (int ky = 0; ky < 3; ky++){
        #pragma unroll
        for (int kx = 0; kx < 3; kx++){
          const ull* wp = reinterpret_cast<const ull*>(s_w + (ci*9 + ky*3 + kx)*COUT);
          ull v0 = pack2(v[ky  ][kx], v[ky  ][kx]);
          ull v1 = pack2(v[ky+1][kx], v[ky+1][kx]);
          #pragma unroll
          for (int kq = 0; kq < NPK; kq++){
            ull w = wp[kq];
            ffma2(acc0[kq], v0, w);
            ffma2(acc1[kq], v1, w);
          }
        }
      }
    }
    #pragma unroll
    for (int kq = 0; kq < NPK; kq++){
      float2 a0 = unpack2(acc0[kq]);
      float2 a1 = unpack2(acc1[kq]);
      if (RELU){
        a0.x = fmaxf(a0.x, 0.f); a0.y = fmaxf(a0.y, 0.f);
        a1.x = fmaxf(a1.x, 0.f); a1.y = fmaxf(a1.y, 0.f);
      }
      size_t o0 = ((size_t)b*COUT + 2*kq)*HW + (size_t)gy0*HP + gx;
      out[o0]        = a0.x;  out[o0 + HW]      = a0.y;
      out[o0 + HP]   = a1.x;  out[o0 + HW + HP] = a1.y;
    }
  } else {
    float a0 = __ldg(&bias[0]), a1 = a0;
    #pragma unroll 1
    for (int ci = 0; ci < CIN; ci++){
      const float* sb = s_in + ci*612 + py2*18 + px;
      float v[4][3];
      #pragma unroll
      for (int dy = 0; dy < 4; dy++)
        #pragma unroll
        for (int dx = 0; dx < 3; dx++) v[dy][dx] = sb[dy*18 + dx];
      #pragma unroll
      for (int ky = 0; ky < 3; ky++)
        #pragma unroll
        for (int kx = 0; kx < 3; kx++){
          float w = s_w[ci*9 + ky*3 + kx];
          a0 += v[ky  ][kx]*w;
          a1 += v[ky+1][kx]*w;
        }
    }
    if (RELU){ a0 = fmaxf(a0, 0.f); a1 = fmaxf(a1, 0.f); }
    size_t o0 = (size_t)b*HW + (size_t)gy0*HP + gx;
    out[o0] = a0; out[o0 + HP] = a1;
  }
}

// ---------------- affinity: wv/wh from 64-channel feature diffs ----------------
__global__ void __launch_bounds__(256) affinity_kernel(const float* __restrict__ logmu){
  int idx = blockIdx.x*256 + threadIdx.x;
  int b = idx >> 16, rem = idx & 65535, i = rem >> 8, j = rem & 255;
  float mu = expf(logmu[0]);
  const float* gp  = g_h2 + (size_t)b*32*HW + rem;
  const float* sp2 = g_h3 + (size_t)b*32*HW + rem;
  bool hasD = (i < 255), hasR = (j < 255);
  float dv = 0.f, dh = 0.f;
  #pragma unroll
  for (int c = 0; c < 32; c++){
    size_t o = (size_t)c*HW;
    float a  = gp[o];
    float a2 = sp2[o];
    if (hasD){ float d1 = gp[o+HP]  - a;  dv += d1*d1;
               float d2 = sp2[o+HP] - a2; dv += d2*d2; }
    if (hasR){ float d1 = gp[o+1]   - a;  dh += d1*d1;
               float d2 = sp2[o+1]  - a2; dh += d2*d2; }
  }
  g_wv[idx] = hasD ? expf(-mu*dv) : 0.f;
  g_wh[idx] = hasR ? expf(-mu*dh) : 0.f;
}

// ---------------- assemble aff output (B,5,H,W): up,dn,lf,rt,center ----------------
__global__ void __launch_bounds__(256) assemble_kernel(float* __restrict__ aff, const float* __restrict__ loglam){
  int idx = blockIdx.x*256 + threadIdx.x;
  int b = idx >> 16, rem = idx & 65535, i = rem >> 8, j = rem & 255;
  float lam = expf(loglam[0]);
  float wdn = g_wv[idx], wrt = g_wh[idx];
  float wup = (i > 0) ? g_wv[idx-HP] : 0.f;
  float wlf = (j > 0) ? g_wh[idx-1]  : 0.f;
  float* o = aff + (size_t)b*5*HW + rem;
  o[0]            = wup;
  o[HW]           = wdn;
  o[(size_t)2*HW] = wlf;
  o[(size_t)3*HW] = wrt;
  o[(size_t)4*HW] = wup + wdn + wlf + wrt + lam;
}

// ---------------- fused CG matvec (+ init variant) ----------------
// A y = deg*y - W y + lam*mask*blocksum8(y)/4096 ; b = lam*mask*source/64 (upsampled)
// INIT: r = b - A x0, p = r, x = x0(=ybic), rs0 += <r,r>, bb += <b,b>
// else: Ap = A p, pAp_k += <p,Ap>
template<bool INIT>
__global__ void __launch_bounds__(256) cg_matvec_kernel(
    const float* __restrict__ vin, const float* __restrict__ source,
    const float* __restrict__ mask, float* __restrict__ xout,
    int k, const float* __restrict__ loglam)
{
  if (!INIT){ if (!(g_scal[k] > g_scal[241])) return; }
  const float lam = expf(loglam[0]);
  __shared__ float sp[34][36];
  __shared__ float scell[4][4];
  __shared__ float sred[8], sred2[8];
  const int b = blockIdx.z;
  const int tx0 = blockIdx.x*32, ty0 = blockIdx.y*32;
  const float* src = INIT ? vin : g_p;
  const float* vb = src + (size_t)b*HW;
  for (int idx = threadIdx.x; idx < 34*34; idx += 256){
    int yy = idx/34, xx = idx - yy*34;
    int gy = ty0+yy-1, gx = tx0+xx-1;
    float v = 0.f;
    if (gy >= 0 && gy < HP && gx >= 0 && gx < HP) v = vb[gy*HP+gx];
    sp[yy][xx] = v;
  }
  if (threadIdx.x < 16) ((float*)scell)[threadIdx.x] = 0.f;
  __syncthreads();

  const int col = threadIdx.x & 31, rb = threadIdx.x >> 5;
  float pc[4], lap[4];
  #pragma unroll
  for (int kk = 0; kk < 4; kk++){
    int rr = rb + 8*kk;
    int gi = ty0 + rr, gj = tx0 + col;
    float c  = sp[rr+1][col+1];
    float up = sp[rr  ][col+1], dn = sp[rr+2][col+1];
    float lf = sp[rr+1][col  ], rt = sp[rr+1][col+2];
    int gidx = (b*HP + gi)*HP + gj;
    float wdn = g_wv[gidx], wrt = g_wh[gidx];
    float wup = (gi > 0) ? g_wv[gidx-HP] : 0.f;
    float wlf = (gj > 0) ? g_wh[gidx-1]  : 0.f;
    pc[kk]  = c;
    lap[kk] = (wup+wdn+wlf+wrt)*c - (wup*up + wdn*dn + wlf*lf + wrt*rt);
    float v = c;
    v += __shfl_down_sync(0xffffffffu, v, 4);
    v += __shfl_down_sync(0xffffffffu, v, 2);
    v += __shfl_down_sync(0xffffffffu, v, 1);
    if ((col & 7) == 0) atomicAdd(&scell[kk][col>>3], v);
  }
  __syncthreads();

  float dot = 0.f, dot2 = 0.f;
  #pragma unroll
  for (int kk = 0; kk < 4; kk++){
    int rr = rb + 8*kk;
    int gi = ty0 + rr, gj = tx0 + col;
    int cy = blockIdx.y*4 + kk, cx = blockIdx.x*4 + (col>>3);
    float m  = mask[b*1024 + cy*32 + cx];
    float Av = lap[kk] + lam*m*scell[kk][col>>3]*(1.f/4096.f);
    int gidx = (b*HP + gi)*HP + gj;
    if (INIT){
      float bv = lam*m*source[b*1024 + cy*32 + cx]*(1.f/64.f);
      float rv = bv - Av;
      g_r[gidx] = rv; g_p[gidx] = rv; xout[gidx] = pc[kk];
      dot += rv*rv; dot2 += bv*bv;
    } else {
      g_Ap[gidx] = Av;
      dot += pc[kk]*Av;
    }
  }
  #pragma unroll
  for (int o = 16; o; o >>= 1){
    dot += __shfl_down_sync(0xffffffffu, dot, o);
    if (INIT) dot2 += __shfl_down_sync(0xffffffffu, dot2, o);
  }
  if (col == 0){ sred[rb] = dot; if (INIT) sred2[rb] = dot2; }
  __syncthreads();
  if (threadIdx.x == 0){
    float s = 0.f, s2 = 0.f;
    #pragma unroll
    for (int i2 = 0; i2 < 8; i2++){ s += sred[i2]; if (INIT) s2 += sred2[i2]; }
    if (INIT){ atomicAdd(&g_scal[0], s); atomicAdd(&g_scal[240], s2); }
    else     { atomicAdd(&g_scal[101+k], s); }
  }
}

__global__ void finalize_kernel(){
  if (threadIdx.x == 0) g_scal[241] = 1e-12f * g_scal[240];   // (tol=1e-6)^2 * <b,b>
}

// x += alpha p ; r -= alpha Ap ; rs_{k+1} += <r,r>
__global__ void __launch_bounds__(256) cg_update_kernel(float* __restrict__ x, int k){
  __shared__ float sred[8];
  float rsk = g_scal[k];
  if (!(rsk > g_scal[241])) return;
  float alpha = rsk / g_scal[101+k];
  int i = blockIdx.x*256 + threadIdx.x;
  float4 pv = ((const float4*)g_p)[i];
  float4 av = ((const float4*)g_Ap)[i];
  float4* xp = (float4*)x;  float4 xv = xp[i];
  float4* rp = (float4*)g_r; float4 rv = rp[i];
  xv.x += alpha*pv.x; xv.y += alpha*pv.y; xv.z += alpha*pv.z; xv.w += alpha*pv.w;
  rv.x -= alpha*av.x; rv.y -= alpha*av.y; rv.z -= alpha*av.z; rv.w -= alpha*av.w;
  xp[i] = xv; rp[i] = rv;
  float s = rv.x*rv.x + rv.y*rv.y + rv.z*rv.z + rv.w*rv.w;
  #pragma unroll
  for (int o = 16; o; o >>= 1) s += __shfl_down_sync(0xffffffffu, s, o);
  if ((threadIdx.x & 31) == 0) sred[threadIdx.x >> 5] = s;
  __syncthreads();
  if (threadIdx.x == 0){
    float t = 0.f;
    #pragma unroll
    for (int i2 = 0; i2 < 8; i2++) t += sred[i2];
    atomicAdd(&g_scal[k+1], t);
  }
}

// p = r + beta p
__global__ void __launch_bounds__(256) cg_pupdate_kernel(int k){
  float rsk = g_scal[k];
  if (!(rsk > g_scal[241])) return;
  float beta = g_scal[k+1] / rsk;
  int i = blockIdx.x*256 + threadIdx.x;
  float4 rv = ((const float4*)g_r)[i];
  float4 pv = ((float4*)g_p)[i];
  pv.x = rv.x + beta*pv.x; pv.y = rv.y + beta*pv.y;
  pv.z = rv.z + beta*pv.z; pv.w = rv.w + beta*pv.w;
  ((float4*)g_p)[i] = pv;
}

// ---------------- host orchestration ----------------
extern "C" void kernel_launch(void* const* d_in, const int* in_sizes, int n_in,
                              void* d_out, int out_size)
{
  const float* guide  = (const float*)d_in[0];
  const float* source = (const float*)d_in[1];
  const float* mask   = (const float*)d_in[2];
  const float* ybic   = (const float*)d_in[3];
  const float* gw1 = (const float*)d_in[4];  const float* gb1 = (const float*)d_in[5];
  const float* gw2 = (const float*)d_in[6];  const float* gb2 = (const float*)d_in[7];
  const float* sw1 = (const float*)d_in[8];  const float* sb1 = (const float*)d_in[9];
  const float* sw2 = (const float*)d_in[10]; const float* sb2 = (const float*)d_in[11];
  const float* vw1 = (const float*)d_in[12]; const float* vb1 = (const float*)d_in[13];
  const float* vw2 = (const float*)d_in[14]; const float* vb2 = (const float*)d_in[15];
  const float* vw3 = (const float*)d_in[16]; const float* vb3 = (const float*)d_in[17];
  const float* loglam = (const float*)d_in[18];
  const float* logmu  = (const float*)d_in[19];

  float* out  = (float*)d_out;
  float* xout = out;                       // y_pred
  float* var  = out + (size_t)NTOT;        // var
  float* aff  = out + (size_t)2*NTOT;      // aff (B,5,H,W)

  float *h1p, *h2p, *h3p;
  cudaGetSymbolAddress((void**)&h1p, g_h1);
  cudaGetSymbolAddress((void**)&h2p, g_h2);
  cudaGetSymbolAddress((void**)&h3p, g_h3);

  auto smemsz = [](int cin, int cout){ return (size_t)(cin*612 + cin*9*cout)*4; };
  cudaFuncSetAttribute(conv3x3_kernel<32,0,32,true>,  cudaFuncAttributeMaxDynamicSharedMemorySize, (int)smemsz(32,32));
  cudaFuncSetAttribute(conv3x3_kernel<32,0,32,false>, cudaFuncAttributeMaxDynamicSharedMemorySize, (int)smemsz(32,32));
  cudaFuncSetAttribute(conv3x3_kernel<32,0,1,false>,  cudaFuncAttributeMaxDynamicSharedMemorySize, (int)smemsz(32,1));

  dim3 gc(16, 8, NB);     // conv tiles: 16x (x), 8x (y), batch
  dim3 gm(8, 8, NB);      // matvec tiles: 32x32

  zero_scal_kernel<<<1,256>>>();

  // variance net: concat(guide, ybic) -> 32 -> 32 -> 1
  conv3x3_kernel<3,1,32,true ><<<gc,256,smemsz(4,32)>>>(guide, ybic, vw1, vb1, h1p);
  conv3x3_kernel<32,0,32,true ><<<gc,256,smemsz(32,32)>>>(h1p, nullptr, vw2, vb2, h2p);
  conv3x3_kernel<32,0,1, false><<<gc,256,smemsz(32,1)>>>(h2p, nullptr, vw3, vb3, var);

  // guide features: guide -> 32 -> 32 (into h2)
  conv3x3_kernel<3,0,32,true ><<<gc,256,smemsz(3,32)>>>(guide, nullptr, gw1, gb1, h1p);
  conv3x3_kernel<32,0,32,false><<<gc,256,smemsz(32,32)>>>(h1p, nullptr, gw2, gb2, h2p);

  // source features: ybic -> 32 -> 32 (into h3)
  conv3x3_kernel<1,0,32,true ><<<gc,256,smemsz(1,32)>>>(ybic, nullptr, sw1, sb1, h1p);
  conv3x3_kernel<32,0,32,false><<<gc,256,smemsz(32,32)>>>(h1p, nullptr, sw2, sb2, h3p);

  // edge weights + aff output
  affinity_kernel<<<NTOT/256,256>>>(logmu);
  assemble_kernel<<<NTOT/256,256>>>(aff, loglam);

  // CG init: r = b - A x0, p = r, x = ybic, rs0, <b,b>
  cg_matvec_kernel<true><<<gm,256>>>(ybic, source, mask, xout, 0, loglam);
  finalize_kernel<<<1,32>>>();

  for (int k = 0; k < 100; k++){
    cg_matvec_kernel<false><<<gm,256>>>(ybic, source, mask, xout, k, loglam);
    cg_update_kernel<<<NTOT/4/256,256>>>(xout, k);
    cg_pupdate_kernel<<<NTOT/4/256,256>>>(k);
  }
}

// round 3
// speedup vs baseline: 1.3213x; 1.3213x over previous
#include <cuda_runtime.h>
#include <math.h>

typedef unsigned long long ull;

#define NB 16
#define HP 256
#define HW 65536
#define NTOT (NB*HW)

// ---------------- static device scratch ----------------
__device__ float g_h1[(size_t)NB*32*HW];
__device__ float g_h2[(size_t)NB*32*HW];
__device__ float g_h3[(size_t)NB*32*HW];
__device__ float g_wv[NTOT];
__device__ float g_wh[NTOT];
__device__ float g_r[NTOT];
__device__ float g_pA[NTOT];
__device__ float g_pB[NTOT];
__device__ float g_Ap[NTOT];
__device__ float g_scal[256];   // [0..100]=rs_k, [101..200]=pAp_k, [240]=<b,b>, [241]=atol2

// ---------------- f32x2 helpers ----------------
__device__ __forceinline__ ull pack2(float a, float b){ ull r; asm("mov.b64 %0, {%1, %2};" : "=l"(r) : "f"(a), "f"(b)); return r; }
__device__ __forceinline__ void ffma2(ull& d, ull a, ull b){ asm("fma.rn.f32x2 %0, %1, %2, %0;" : "+l"(d) : "l"(a), "l"(b)); }
__device__ __forceinline__ float2 unpack2(ull v){ float2 f; asm("mov.b64 {%0, %1}, %2;" : "=f"(f.x), "=f"(f.y) : "l"(v)); return f; }

__global__ void zero_scal_kernel(){ g_scal[threadIdx.x] = 0.f; }

// =====================================================================
// conv3x3 pair kernel: COUT%8==0. Tile 16x16 pixels. 256 threads.
// thread = cog(2b) x slot(6b); slot -> px(0..15), py=4*(slot>>4).
// Each thread: 4 pixels x PPG f32x2 output-channel pairs.
// Input channels processed in chunks of <=8 staged in smem.
// =====================================================================
template<int CINA,int CINB,int COUT,bool RELU>
__global__ void __launch_bounds__(256,2) conv3x3_pair(
    const float* __restrict__ inA, const float* __restrict__ inB,
    const float* __restrict__ W, const float* __restrict__ bias,
    float* __restrict__ out)
{
  constexpr int CIN   = CINA + CINB;
  constexpr int CHUNK = (CIN >= 8) ? 8 : CIN;
  constexpr int PPG   = COUT / 8;            // pairs per cog

  __shared__ float s_in[CHUNK][18][20];
  __shared__ float s_w[CHUNK*9*COUT];

  const int tid  = threadIdx.x;
  const int cog  = tid >> 6;
  const int slot = tid & 63;
  const int px   = slot & 15;
  const int py   = (slot >> 4) << 2;
  const int b    = blockIdx.z;
  const int tx0  = blockIdx.x*16, ty0 = blockIdx.y*16;

  ull acc[4][PPG];
  #pragma unroll
  for (int q = 0; q < PPG; q++){
    int co0 = 2*(cog*PPG + q);
    ull bz = pack2(__ldg(&bias[co0]), __ldg(&bias[co0+1]));
    #pragma unroll
    for (int pix = 0; pix < 4; pix++) acc[pix][q] = bz;
  }

  #pragma unroll 1
  for (int c0 = 0; c0 < CIN; c0 += CHUNK){
    if (c0) __syncthreads();
    // stage weights for this chunk: layout [(cl*9+tap)*COUT + co]
    for (int idx = tid; idx < CHUNK*9*COUT; idx += 256){
      int cl = idx/(9*COUT); int r = idx - cl*9*COUT;
      int tap = r/COUT; int co = r - tap*COUT;
      s_w[idx] = W[(size_t)co*CIN*9 + (size_t)(c0+cl)*9 + tap];
    }
    // stage input halo tile (18x18) for CHUNK channels
    for (int idx = tid; idx < CHUNK*324; idx += 256){
      int cl = idx/324; int rem = idx - cl*324;
      int yy = rem/18, xx = rem - yy*18;
      int gy = ty0+yy-1, gx = tx0+xx-1;
      int ci = c0 + cl;
      const float* src = (ci < CINA) ? (inA + ((size_t)b*CINA + ci)*HW)
                                     : (inB + ((size_t)b*CINB + (ci-CINA))*HW);
      float v = 0.f;
      if (gy >= 0 && gy < HP && gx >= 0 && gx < HP) v = src[gy*HP+gx];
      s_in[cl][yy][xx] = v;
    }
    __syncthreads();

    #pragma unroll 1
    for (int cl = 0; cl < CHUNK; cl++){
      ull vp[6][3];
      #pragma unroll
      for (int dy = 0; dy < 6; dy++)
        #pragma unroll
        for (int dx = 0; dx < 3; dx++){
          float f = s_in[cl][py+dy][px+dx];
          vp[dy][dx] = pack2(f, f);
        }
      #pragma unroll
      for (int ky = 0; ky < 3; ky++)
        #pragma unroll
        for (int kx = 0; kx < 3; kx++){
          const ull* wp = reinterpret_cast<const ull*>(s_w + (cl*9 + ky*3 + kx)*COUT) + cog*PPG;
          #pragma unroll
          for (int q = 0; q < PPG; q++){
            ull w = wp[q];
            #pragma unroll
            for (int pix = 0; pix < 4; pix++)
              ffma2(acc[pix][q], vp[pix+ky][kx], w);
          }
        }
    }
  }

  #pragma unroll
  for (int q = 0; q < PPG; q++){
    int co0 = 2*(cog*PPG + q);
    #pragma unroll
    for (int pix = 0; pix < 4; pix++){
      float2 a = unpack2(acc[pix][q]);
      if (RELU){ a.x = fmaxf(a.x, 0.f); a.y = fmaxf(a.y, 0.f); }
      size_t o = ((size_t)b*COUT + co0)*HW + (size_t)(ty0+py+pix)*HP + (tx0+px);
      out[o] = a.x; out[o + HW] = a.y;
    }
  }
}

// conv 32 -> 1 (variance head). Tile 32x32, thread = 4 vertical pixels.
__global__ void __launch_bounds__(256) conv3x3_one(
    const float* __restrict__ in, const float* __restrict__ W,
    const float* __restrict__ bias, float* __restrict__ out)
{
  __shared__ float s_in[8][34][36];
  __shared__ float s_w[8*9];
  const int tid = threadIdx.x;
  const int px = tid & 31;
  const int py = (tid >> 5) << 2;
  const int b = blockIdx.z;
  const int tx0 = blockIdx.x*32, ty0 = blockIdx.y*32;

  float acc[4];
  float bz = __ldg(&bias[0]);
  #pragma unroll
  for (int pix = 0; pix < 4; pix++) acc[pix] = bz;

  #pragma unroll 1
  for (int c0 = 0; c0 < 32; c0 += 8){
    if (c0) __syncthreads();
    if (tid < 72) s_w[tid] = W[c0*9 + tid];
    for (int idx = tid; idx < 8*1156; idx += 256){
      int cl = idx/1156; int rem = idx - cl*1156;
      int yy = rem/34, xx = rem - yy*34;
      int gy = ty0+yy-1, gx = tx0+xx-1;
      float v = 0.f;
      if (gy >= 0 && gy < HP && gx >= 0 && gx < HP)
        v = in[((size_t)b*32 + c0+cl)*HW + gy*HP + gx];
      s_in[cl][yy][xx] = v;
    }
    __syncthreads();
    #pragma unroll 1
    for (int cl = 0; cl < 8; cl++){
      float v[6][3];
      #pragma unroll
      for (int dy = 0; dy < 6; dy++)
        #pragma unroll
        for (int dx = 0; dx < 3; dx++) v[dy][dx] = s_in[cl][py+dy][px+dx];
      #pragma unroll
      for (int ky = 0; ky < 3; ky++)
        #pragma unroll
        for (int kx = 0; kx < 3; kx++){
          float w = s_w[cl*9 + ky*3 + kx];
          #pragma unroll
          for (int pix = 0; pix < 4; pix++) acc[pix] += v[pix+ky][kx]*w;
        }
    }
  }
  #pragma unroll
  for (int pix = 0; pix < 4; pix++)
    out[(size_t)b*HW + (size_t)(ty0+py+pix)*HP + (tx0+px)] = acc[pix];
}

// ---------------- affinity: wv/wh from 64-channel feature diffs ----------------
__global__ void __launch_bounds__(256) affinity_kernel(const float* __restrict__ logmu){
  int idx = blockIdx.x*256 + threadIdx.x;
  int b = idx >> 16, rem = idx & 65535, i = rem >> 8, j = rem & 255;
  float mu = expf(logmu[0]);
  const float* gp  = g_h2 + (size_t)b*32*HW + rem;
  const float* sp2 = g_h3 + (size_t)b*32*HW + rem;
  bool hasD = (i < 255), hasR = (j < 255);
  float dv = 0.f, dh = 0.f;
  #pragma unroll
  for (int c = 0; c < 32; c++){
    size_t o = (size_t)c*HW;
    float a  = gp[o];
    float a2 = sp2[o];
    if (hasD){ float d1 = gp[o+HP]  - a;  dv += d1*d1;
               float d2 = sp2[o+HP] - a2; dv += d2*d2; }
    if (hasR){ float d1 = gp[o+1]   - a;  dh += d1*d1;
               float d2 = sp2[o+1]  - a2; dh += d2*d2; }
  }
  g_wv[idx] = hasD ? expf(-mu*dv) : 0.f;
  g_wh[idx] = hasR ? expf(-mu*dh) : 0.f;
}

// ---------------- assemble aff output (B,5,H,W) ----------------
__global__ void __launch_bounds__(256) assemble_kernel(float* __restrict__ aff, const float* __restrict__ loglam){
  int idx = blockIdx.x*256 + threadIdx.x;
  int b = idx >> 16, rem = idx & 65535, i = rem >> 8, j = rem & 255;
  float lam = expf(loglam[0]);
  float wdn = g_wv[idx], wrt = g_wh[idx];
  float wup = (i > 0) ? g_wv[idx-HP] : 0.f;
  float wlf = (j > 0) ? g_wh[idx-1]  : 0.f;
  float* o = aff + (size_t)b*5*HW + rem;
  o[0]            = wup;
  o[HW]           = wdn;
  o[(size_t)2*HW] = wlf;
  o[(size_t)3*HW] = wrt;
  o[(size_t)4*HW] = wup + wdn + wlf + wrt + lam;
}

// ---------------- fused CG matvec with ping-pong p buffers ----------------
// INIT: r = b - A x0, p(=pA) = r, x = x0, rs0 += <r,r>, bb += <b,b>
// k==0: Ap = A pA (p_in = pA used directly, no p update)
// k>=1: p_new = r + beta*p_prev computed in-tile (incl halo) from STABLE r/p_prev,
//       interior written to p_out (different buffer -> no race), Ap = A p_new.
template<bool INIT>
__global__ void __launch_bounds__(256) cg_matvec_kernel(
    const float* __restrict__ vin, const float* __restrict__ source,
    const float* __restrict__ mask, float* __restrict__ xout,
    const float* __restrict__ p_prev, float* __restrict__ p_out,
    int k, const float* __restrict__ loglam)
{
  if (!INIT){ if (!(g_scal[k] > g_scal[241])) return; }
  const float lam = expf(loglam[0]);
  __shared__ float sp[34][36];
  __shared__ float scell[4][4];
  __shared__ float sred[8], sred2[8];
  const int b = blockIdx.z;
  const int tx0 = blockIdx.x*32, ty0 = blockIdx.y*32;

  if (INIT || k == 0){
    const float* vb = (INIT ? vin : p_prev) + (size_t)b*HW;
    for (int idx = threadIdx.x; idx < 34*34; idx += 256){
      int yy = idx/34, xx = idx - yy*34;
      int gy = ty0+yy-1, gx = tx0+xx-1;
      float v = 0.f;
      if (gy >= 0 && gy < HP && gx >= 0 && gx < HP) v = vb[gy*HP+gx];
      sp[yy][xx] = v;
    }
  } else {
    float beta = g_scal[k] / g_scal[k-1];
    const float* rb = g_r + (size_t)b*HW;
    const float* pb = p_prev + (size_t)b*HW;
    float* po = p_out + (size_t)b*HW;
    for (int idx = threadIdx.x; idx < 34*34; idx += 256){
      int yy = idx/34, xx = idx - yy*34;
      int gy = ty0+yy-1, gx = tx0+xx-1;
      float v = 0.f;
      if (gy >= 0 && gy < HP && gx >= 0 && gx < HP){
        int o = gy*HP+gx;
        v = rb[o] + beta*pb[o];
        if (yy >= 1 && yy <= 32 && xx >= 1 && xx <= 32) po[o] = v;
      }
      sp[yy][xx] = v;
    }
  }
  if (threadIdx.x < 16) ((float*)scell)[threadIdx.x] = 0.f;
  __syncthreads();

  const int col = threadIdx.x & 31, rb_ = threadIdx.x >> 5;
  float pc[4], lap[4];
  #pragma unroll
  for (int kk = 0; kk < 4; kk++){
    int rr = rb_ + 8*kk;
    int gi = ty0 + rr, gj = tx0 + col;
    float c  = sp[rr+1][col+1];
    float up = sp[rr  ][col+1], dn = sp[rr+2][col+1];
    float lf = sp[rr+1][col  ], rt = sp[rr+1][col+2];
    int gidx = (b*HP + gi)*HP + gj;
    float wdn = g_wv[gidx], wrt = g_wh[gidx];
    float wup = (gi > 0) ? g_wv[gidx-HP] : 0.f;
    float wlf = (gj > 0) ? g_wh[gidx-1]  : 0.f;
    pc[kk]  = c;
    lap[kk] = (wup+wdn+wlf+wrt)*c - (wup*up + wdn*dn + wlf*lf + wrt*rt);
    float v = c;
    v += __shfl_down_sync(0xffffffffu, v, 4);
    v += __shfl_down_sync(0xffffffffu, v, 2);
    v += __shfl_down_sync(0xffffffffu, v, 1);
    if ((col & 7) == 0) atomicAdd(&scell[kk][col>>3], v);
  }
  __syncthreads();

  float dot = 0.f, dot2 = 0.f;
  #pragma unroll
  for (int kk = 0; kk < 4; kk++){
    int rr = rb_ + 8*kk;
    int gi = ty0 + rr, gj = tx0 + col;
    int cy = blockIdx.y*4 + kk, cx = blockIdx.x*4 + (col>>3);
    float m  = mask[b*1024 + cy*32 + cx];
    float Av = lap[kk] + lam*m*scell[kk][col>>3]*(1.f/4096.f);
    int gidx = (b*HP + gi)*HP + gj;
    if (INIT){
      float bv = lam*m*source[b*1024 + cy*32 + cx]*(1.f/64.f);
      float rv = bv - Av;
      g_r[gidx] = rv; p_out[gidx] = rv; xout[gidx] = pc[kk];
      dot += rv*rv; dot2 += bv*bv;
    } else {
      g_Ap[gidx] = Av;
      dot += pc[kk]*Av;
    }
  }
  #pragma unroll
  for (int o = 16; o; o >>= 1){
    dot += __shfl_down_sync(0xffffffffu, dot, o);
    if (INIT) dot2 += __shfl_down_sync(0xffffffffu, dot2, o);
  }
  if (col == 0){ sred[rb_] = dot; if (INIT) sred2[rb_] = dot2; }
  __syncthreads();
  if (threadIdx.x == 0){
    float s = 0.f, s2 = 0.f;
    #pragma unroll
    for (int i2 = 0; i2 < 8; i2++){ s += sred[i2]; if (INIT) s2 += sred2[i2]; }
    if (INIT){ atomicAdd(&g_scal[0], s); atomicAdd(&g_scal[240], s2); }
    else     { atomicAdd(&g_scal[101+k], s); }
  }
}

__global__ void finalize_kernel(){
  if (threadIdx.x == 0) g_scal[241] = 1e-12f * g_scal[240];
}

// x += alpha p ; r -= alpha Ap ; rs_{k+1} += <r,r>
__global__ void __launch_bounds__(256) cg_update_kernel(float* __restrict__ x,
                                                        const float* __restrict__ p_cur, int k){
  __shared__ float sred[8];
  float rsk = g_scal[k];
  if (!(rsk > g_scal[241])) return;
  float alpha = rsk / g_scal[101+k];
  int i = blockIdx.x*256 + threadIdx.x;
  float4 pv = ((const float4*)p_cur)[i];
  float4 av = ((const float4*)g_Ap)[i];
  float4* xp = (float4*)x;  float4 xv = xp[i];
  float4* rp = (float4*)g_r; float4 rv = rp[i];
  xv.x += alpha*pv.x; xv.y += alpha*pv.y; xv.z += alpha*pv.z; xv.w += alpha*pv.w;
  rv.x -= alpha*av.x; rv.y -= alpha*av.y; rv.z -= alpha*av.z; rv.w -= alpha*av.w;
  xp[i] = xv; rp[i] = rv;
  float s = rv.x*rv.x + rv.y*rv.y + rv.z*rv.z + rv.w*rv.w;
  #pragma unroll
  for (int o = 16; o; o >>= 1) s += __shfl_down_sync(0xffffffffu, s, o);
  if ((threadIdx.x & 31) == 0) sred[threadIdx.x >> 5] = s;
  __syncthreads();
  if (threadIdx.x == 0){
    float t = 0.f;
    #pragma unroll
    for (int i2 = 0; i2 < 8; i2++) t += sred[i2];
    atomicAdd(&g_scal[k+1], t);
  }
}

// ---------------- host orchestration ----------------
extern "C" void kernel_launch(void* const* d_in, const int* in_sizes, int n_in,
                              void* d_out, int out_size)
{
  const float* guide  = (const float*)d_in[0];
  const float* source = (const float*)d_in[1];
  const float* mask   = (const float*)d_in[2];
  const float* ybic   = (const float*)d_in[3];
  const float* gw1 = (const float*)d_in[4];  const float* gb1 = (const float*)d_in[5];
  const float* gw2 = (const float*)d_in[6];  const float* gb2 = (const float*)d_in[7];
  const float* sw1 = (const float*)d_in[8];  const float* sb1 = (const float*)d_in[9];
  const float* sw2 = (const float*)d_in[10]; const float* sb2 = (const float*)d_in[11];
  const float* vw1 = (const float*)d_in[12]; const float* vb1 = (const float*)d_in[13];
  const float* vw2 = (const float*)d_in[14]; const float* vb2 = (const float*)d_in[15];
  const float* vw3 = (const float*)d_in[16]; const float* vb3 = (const float*)d_in[17];
  const float* loglam = (const float*)d_in[18];
  const float* logmu  = (const float*)d_in[19];

  float* out  = (float*)d_out;
  float* xout = out;
  float* var  = out + (size_t)NTOT;
  float* aff  = out + (size_t)2*NTOT;

  float *h1p, *h2p, *h3p, *pAp_, *pBp_;
  cudaGetSymbolAddress((void**)&h1p, g_h1);
  cudaGetSymbolAddress((void**)&h2p, g_h2);
  cudaGetSymbolAddress((void**)&h3p, g_h3);
  cudaGetSymbolAddress((void**)&pAp_, g_pA);
  cudaGetSymbolAddress((void**)&pBp_, g_pB);

  dim3 gc(16, 16, NB);    // conv tiles 16x16
  dim3 g1(8, 8, NB);      // 32x32 tiles
  dim3 gm(8, 8, NB);      // matvec tiles 32x32

  zero_scal_kernel<<<1,256>>>();

  // variance net: concat(guide, ybic) -> 32 -> 32 -> 1
  conv3x3_pair<3,1,32,true ><<<gc,256>>>(guide, ybic, vw1, vb1, h1p);
  conv3x3_pair<32,0,32,true ><<<gc,256>>>(h1p, nullptr, vw2, vb2, h2p);
  conv3x3_one<<<g1,256>>>(h2p, vw3, vb3, var);

  // guide features: guide -> 32 -> 32
  conv3x3_pair<3,0,32,true ><<<gc,256>>>(guide, nullptr, gw1, gb1, h1p);
  conv3x3_pair<32,0,32,false><<<gc,256>>>(h1p, nullptr, gw2, gb2, h2p);

  // source features: ybic -> 32 -> 32
  conv3x3_pair<1,0,32,true ><<<gc,256>>>(ybic, nullptr, sw1, sb1, h1p);
  conv3x3_pair<32,0,32,false><<<gc,256>>>(h1p, nullptr, sw2, sb2, h3p);

  // edge weights + aff output
  affinity_kernel<<<NTOT/256,256>>>(logmu);
  assemble_kernel<<<NTOT/256,256>>>(aff, loglam);

  // CG init: p(=pA) = r = b - A x0
  cg_matvec_kernel<true><<<gm,256>>>(ybic, source, mask, xout, nullptr, pAp_, 0, loglam);
  finalize_kernel<<<1,32>>>();

  // iteration k: p_in = (k==0) ? pA : prev buffer; k>=1 writes p_new into the other buffer.
  float* pin = pAp_;
  for (int k = 0; k < 100; k++){
    float* pout = (k == 0) ? pAp_ : ((pin == pAp_) ? pBp_ : pAp_);
    cg_matvec_kernel<false><<<gm,256>>>(ybic, source, mask, xout, pin, pout, k, loglam);
    float* pcur = (k == 0) ? pAp_ : pout;
    cg_update_kernel<<<NTOT/4/256,256>>>(xout, pcur, k);
    pin = pcur;
  }
}

// round 5
// speedup vs baseline: 1.3396x; 1.0138x over previous
#include <cuda_runtime.h>
#include <math.h>

typedef unsigned long long ull;

#define NB 16
#define HP 256
#define HW 65536
#define NTOT (NB*HW)

// g_scal layout
#define GAM   0     // gamma[k] = <r_k,r_k>,   k=0..100
#define DEL   110   // delta[k] = <r_k,w_k>
#define ALF   220   // alpha[k]
#define BBIDX 330   // <b,b>
#define ATOL2 331   // 1e-12 * <b,b>

// ---------------- static device scratch ----------------
__device__ float g_h1[(size_t)NB*32*HW];   // conv hidden scratch
__device__ float g_h2[(size_t)NB*32*HW];   // g-features
__device__ float g_h3[(size_t)NB*32*HW];   // s-features
__device__ float g_wv[NTOT];
__device__ float g_wh[NTOT];
__device__ float g_R0[NTOT];
__device__ float g_R1[NTOT];
__device__ float g_S0[NTOT];
__device__ float g_S1[NTOT];
__device__ float g_W0[NTOT];
__device__ float g_W1[NTOT];
__device__ float g_P [NTOT];
__device__ float g_scal[512];

// ---------------- f32x2 helpers ----------------
__device__ __forceinline__ ull pack2(float a, float b){ ull r; asm("mov.b64 %0, {%1, %2};" : "=l"(r) : "f"(a), "f"(b)); return r; }
__device__ __forceinline__ void ffma2(ull& d, ull a, ull b){ asm("fma.rn.f32x2 %0, %1, %2, %0;" : "+l"(d) : "l"(a), "l"(b)); }
__device__ __forceinline__ float2 unpack2(ull v){ float2 f; asm("mov.b64 {%0, %1}, %2;" : "=f"(f.x), "=f"(f.y) : "l"(v)); return f; }

__global__ void zero_scal_kernel(){ g_scal[threadIdx.x] = 0.f; g_scal[256+threadIdx.x] = 0.f; }

// =====================================================================
// conv3x3 pair kernel (near f32x2 fma floor)
// =====================================================================
template<int CINA,int CINB,int COUT,bool RELU>
__global__ void __launch_bounds__(256,2) conv3x3_pair(
    const float* __restrict__ inA, const float* __restrict__ inB,
    const float* __restrict__ W, const float* __restrict__ bias,
    float* __restrict__ out)
{
  constexpr int CIN   = CINA + CINB;
  constexpr int CHUNK = (CIN >= 8) ? 8 : CIN;
  constexpr int PPG   = COUT / 8;

  __shared__ float s_in[CHUNK][18][20];
  __shared__ float s_w[CHUNK*9*COUT];

  const int tid  = threadIdx.x;
  const int cog  = tid >> 6;
  const int slot = tid & 63;
  const int px   = slot & 15;
  const int py   = (slot >> 4) << 2;
  const int b    = blockIdx.z;
  const int tx0  = blockIdx.x*16, ty0 = blockIdx.y*16;

  ull acc[4][PPG];
  #pragma unroll
  for (int q = 0; q < PPG; q++){
    int co0 = 2*(cog*PPG + q);
    ull bz = pack2(__ldg(&bias[co0]), __ldg(&bias[co0+1]));
    #pragma unroll
    for (int pix = 0; pix < 4; pix++) acc[pix][q] = bz;
  }

  #pragma unroll 1
  for (int c0 = 0; c0 < CIN; c0 += CHUNK){
    if (c0) __syncthreads();
    for (int idx = tid; idx < CHUNK*9*COUT; idx += 256){
      int cl = idx/(9*COUT); int r = idx - cl*9*COUT;
      int tap = r/COUT; int co = r - tap*COUT;
      s_w[idx] = W[(size_t)co*CIN*9 + (size_t)(c0+cl)*9 + tap];
    }
    for (int idx = tid; idx < CHUNK*324; idx += 256){
      int cl = idx/324; int rem = idx - cl*324;
      int yy = rem/18, xx = rem - yy*18;
      int gy = ty0+yy-1, gx = tx0+xx-1;
      int ci = c0 + cl;
      const float* src = (ci < CINA) ? (inA + ((size_t)b*CINA + ci)*HW)
                                     : (inB + ((size_t)b*CINB + (ci-CINA))*HW);
      float v = 0.f;
      if (gy >= 0 && gy < HP && gx >= 0 && gx < HP) v = src[gy*HP+gx];
      s_in[cl][yy][xx] = v;
    }
    __syncthreads();

    #pragma unroll 1
    for (int cl = 0; cl < CHUNK; cl++){
      ull vp[6][3];
      #pragma unroll
      for (int dy = 0; dy < 6; dy++)
        #pragma unroll
        for (int dx = 0; dx < 3; dx++){
          float f = s_in[cl][py+dy][px+dx];
          vp[dy][dx] = pack2(f, f);
        }
      #pragma unroll
      for (int ky = 0; ky < 3; ky++)
        #pragma unroll
        for (int kx = 0; kx < 3; kx++){
          const ull* wp = reinterpret_cast<const ull*>(s_w + (cl*9 + ky*3 + kx)*COUT) + cog*PPG;
          #pragma unroll
          for (int q = 0; q < PPG; q++){
            ull w = wp[q];
            #pragma unroll
            for (int pix = 0; pix < 4; pix++)
              ffma2(acc[pix][q], vp[pix+ky][kx], w);
          }
        }
    }
  }

  #pragma unroll
  for (int q = 0; q < PPG; q++){
    int co0 = 2*(cog*PPG + q);
    #pragma unroll
    for (int pix = 0; pix < 4; pix++){
      float2 a = unpack2(acc[pix][q]);
      if (RELU){ a.x = fmaxf(a.x, 0.f); a.y = fmaxf(a.y, 0.f); }
      size_t o = ((size_t)b*COUT + co0)*HW + (size_t)(ty0+py+pix)*HP + (tx0+px);
      out[o] = a.x; out[o + HW] = a.y;
    }
  }
}

// conv 32 -> 1 (variance head)
__global__ void __launch_bounds__(256) conv3x3_one(
    const float* __restrict__ in, const float* __restrict__ W,
    const float* __restrict__ bias, float* __restrict__ out)
{
  __shared__ float s_in[8][34][36];
  __shared__ float s_w[8*9];
  const int tid = threadIdx.x;
  const int px = tid & 31;
  const int py = (tid >> 5) << 2;
  const int b = blockIdx.z;
  const int tx0 = blockIdx.x*32, ty0 = blockIdx.y*32;

  float acc[4];
  float bz = __ldg(&bias[0]);
  #pragma unroll
  for (int pix = 0; pix < 4; pix++) acc[pix] = bz;

  #pragma unroll 1
  for (int c0 = 0; c0 < 32; c0 += 8){
    if (c0) __syncthreads();
    if (tid < 72) s_w[tid] = W[c0*9 + tid];
    for (int idx = tid; idx < 8*1156; idx += 256){
      int cl = idx/1156; int rem = idx - cl*1156;
      int yy = rem/34, xx = rem - yy*34;
      int gy = ty0+yy-1, gx = tx0+xx-1;
      float v = 0.f;
      if (gy >= 0 && gy < HP && gx >= 0 && gx < HP)
        v = in[((size_t)b*32 + c0+cl)*HW + gy*HP + gx];
      s_in[cl][yy][xx] = v;
    }
    __syncthreads();
    #pragma unroll 1
    for (int cl = 0; cl < 8; cl++){
      float v[6][3];
      #pragma unroll
      for (int dy = 0; dy < 6; dy++)
        #pragma unroll
        for (int dx = 0; dx < 3; dx++) v[dy][dx] = s_in[cl][py+dy][px+dx];
      #pragma unroll
      for (int ky = 0; ky < 3; ky++)
        #pragma unroll
        for (int kx = 0; kx < 3; kx++){
          float w = s_w[cl*9 + ky*3 + kx];
          #pragma unroll
          for (int pix = 0; pix < 4; pix++) acc[pix] += v[pix+ky][kx]*w;
        }
    }
  }
  #pragma unroll
  for (int pix = 0; pix < 4; pix++)
    out[(size_t)b*HW + (size_t)(ty0+py+pix)*HP + (tx0+px)] = acc[pix];
}

// ---------------- affinity ----------------
__global__ void __launch_bounds__(256) affinity_kernel(const float* __restrict__ logmu){
  int idx = blockIdx.x*256 + threadIdx.x;
  int b = idx >> 16, rem = idx & 65535, i = rem >> 8, j = rem & 255;
  float mu = expf(logmu[0]);
  const float* gp  = g_h2 + (size_t)b*32*HW + rem;
  const float* sp2 = g_h3 + (size_t)b*32*HW + rem;
  bool hasD = (i < 255), hasR = (j < 255);
  float dv = 0.f, dh = 0.f;
  #pragma unroll
  for (int c = 0; c < 32; c++){
    size_t o = (size_t)c*HW;
    float a  = gp[o];
    float a2 = sp2[o];
    if (hasD){ float d1 = gp[o+HP]  - a;  dv += d1*d1;
               float d2 = sp2[o+HP] - a2; dv += d2*d2; }
    if (hasR){ float d1 = gp[o+1]   - a;  dh += d1*d1;
               float d2 = sp2[o+1]  - a2; dh += d2*d2; }
  }
  g_wv[idx] = hasD ? expf(-mu*dv) : 0.f;
  g_wh[idx] = hasR ? expf(-mu*dh) : 0.f;
}

// ---------------- assemble aff output (B,5,H,W) ----------------
__global__ void __launch_bounds__(256) assemble_kernel(float* __restrict__ aff, const float* __restrict__ loglam){
  int idx = blockIdx.x*256 + threadIdx.x;
  int b = idx >> 16, rem = idx & 65535, i = rem >> 8, j = rem & 255;
  float lam = expf(loglam[0]);
  float wdn = g_wv[idx], wrt = g_wh[idx];
  float wup = (i > 0) ? g_wv[idx-HP] : 0.f;
  float wlf = (j > 0) ? g_wh[idx-1]  : 0.f;
  float* o = aff + (size_t)b*5*HW + rem;
  o[0]            = wup;
  o[HW]           = wdn;
  o[(size_t)2*HW] = wlf;
  o[(size_t)3*HW] = wrt;
  o[(size_t)4*HW] = wup + wdn + wlf + wrt + lam;
}

// ---------------- matvec phase2 ----------------
// Av for interior 32x32 from sp (v on halo), write Wout_b, reduce
// d1 += v*v into g_scal[i1] (if i1>=0), d2 += v*Av into g_scal[i2].
__device__ __forceinline__ void matvec_phase2(
    float sp[34][36], float lam, const float* __restrict__ mask,
    int b, int tx0, int ty0, float* __restrict__ Wout_b, int i1, int i2)
{
  __shared__ float scell[4][4];
  __shared__ float sred[8], sred2[8];
  const int tid = threadIdx.x;
  if (tid < 16) ((float*)scell)[tid] = 0.f;
  __syncthreads();

  const int col = tid & 31, rb_ = tid >> 5;
  float pc[4], lap[4];
  #pragma unroll
  for (int kk = 0; kk < 4; kk++){
    int rr = rb_ + 8*kk;
    int gi = ty0 + rr, gj = tx0 + col;
    float c  = sp[rr+1][col+1];
    float up = sp[rr  ][col+1], dn = sp[rr+2][col+1];
    float lf = sp[rr+1][col  ], rt = sp[rr+1][col+2];
    int gidx = (b*HP + gi)*HP + gj;
    float wdn = g_wv[gidx], wrt = g_wh[gidx];
    float wup = (gi > 0) ? g_wv[gidx-HP] : 0.f;
    float wlf = (gj > 0) ? g_wh[gidx-1]  : 0.f;
    pc[kk]  = c;
    lap[kk] = (wup+wdn+wlf+wrt)*c - (wup*up + wdn*dn + wlf*lf + wrt*rt);
    float v = c;
    v += __shfl_down_sync(0xffffffffu, v, 4);
    v += __shfl_down_sync(0xffffffffu, v, 2);
    v += __shfl_down_sync(0xffffffffu, v, 1);
    if ((col & 7) == 0) atomicAdd(&scell[kk][col>>3], v);
  }
  __syncthreads();

  float d1 = 0.f, d2 = 0.f;
  #pragma unroll
  for (int kk = 0; kk < 4; kk++){
    int rr = rb_ + 8*kk;
    int gi = ty0 + rr, gj = tx0 + col;
    int cy = blockIdx.y*4 + kk, cx = blockIdx.x*4 + (col>>3);
    float m  = mask[b*1024 + cy*32 + cx];
    float Av = lap[kk] + lam*m*scell[kk][col>>3]*(1.f/4096.f);
    Wout_b[gi*HP + gj] = Av;
    d1 += pc[kk]*pc[kk];
    d2 += pc[kk]*Av;
  }
  #pragma unroll
  for (int o = 16; o; o >>= 1){
    d1 += __shfl_down_sync(0xffffffffu, d1, o);
    d2 += __shfl_down_sync(0xffffffffu, d2, o);
  }
  if (col == 0){ sred[rb_] = d1; sred2[rb_] = d2; }
  __syncthreads();
  if (tid == 0){
    float s1 = 0.f, s2 = 0.f;
    #pragma unroll
    for (int i = 0; i < 8; i++){ s1 += sred[i]; s2 += sred2[i]; }
    if (i1 >= 0) atomicAdd(&g_scal[i1], s1);
    atomicAdd(&g_scal[i2], s2);
  }
}

// ---------------- CG init: r0 = b - A x0, X = x0; reduce gamma0, <b,b> ----------------
__global__ void __launch_bounds__(256) cg_init_kernel(
    const float* __restrict__ x0, const float* __restrict__ source,
    const float* __restrict__ mask, float* __restrict__ X,
    float* __restrict__ R0, const float* __restrict__ loglam)
{
  const float lam = expf(loglam[0]);
  __shared__ float sp[34][36];
  __shared__ float scell[4][4];
  __shared__ float sred[8], sred2[8];
  const int b = blockIdx.z;
  const int tx0 = blockIdx.x*32, ty0 = blockIdx.y*32;
  const float* vb = x0 + (size_t)b*HW;
  for (int idx = threadIdx.x; idx < 34*34; idx += 256){
    int yy = idx/34, xx = idx - yy*34;
    int gy = ty0+yy-1, gx = tx0+xx-1;
    float v = 0.f;
    if (gy >= 0 && gy < HP && gx >= 0 && gx < HP) v = vb[gy*HP+gx];
    sp[yy][xx] = v;
  }
  if (threadIdx.x < 16) ((float*)scell)[threadIdx.x] = 0.f;
  __syncthreads();

  const int col = threadIdx.x & 31, rb_ = threadIdx.x >> 5;
  float pc[4], lap[4];
  #pragma unroll
  for (int kk = 0; kk < 4; kk++){
    int rr = rb_ + 8*kk;
    int gi = ty0 + rr, gj = tx0 + col;
    float c  = sp[rr+1][col+1];
    float up = sp[rr  ][col+1], dn = sp[rr+2][col+1];
    float lf = sp[rr+1][col  ], rt = sp[rr+1][col+2];
    int gidx = (b*HP + gi)*HP + gj;
    float wdn = g_wv[gidx], wrt = g_wh[gidx];
    float wup = (gi > 0) ? g_wv[gidx-HP] : 0.f;
    float wlf = (gj > 0) ? g_wh[gidx-1]  : 0.f;
    pc[kk]  = c;
    lap[kk] = (wup+wdn+wlf+wrt)*c - (wup*up + wdn*dn + wlf*lf + wrt*rt);
    float v = c;
    v += __shfl_down_sync(0xffffffffu, v, 4);
    v += __shfl_down_sync(0xffffffffu, v, 2);
    v += __shfl_down_sync(0xffffffffu, v, 1);
    if ((col & 7) == 0) atomicAdd(&scell[kk][col>>3], v);
  }
  __syncthreads();

  float d1 = 0.f, d2 = 0.f;
  #pragma unroll
  for (int kk = 0; kk < 4; kk++){
    int rr = rb_ + 8*kk;
    int gi = ty0 + rr, gj = tx0 + col;
    int cy = blockIdx.y*4 + kk, cx = blockIdx.x*4 + (col>>3);
    float m  = mask[b*1024 + cy*32 + cx];
    float Av = lap[kk] + lam*m*scell[kk][col>>3]*(1.f/4096.f);
    int gidx = (b*HP + gi)*HP + gj;
    float bv = lam*m*source[b*1024 + cy*32 + cx]*(1.f/64.f);
    float rv = bv - Av;
    R0[gidx] = rv; X[gidx] = pc[kk];
    d1 += rv*rv; d2 += bv*bv;
  }
  #pragma unroll
  for (int o = 16; o; o >>= 1){
    d1 += __shfl_down_sync(0xffffffffu, d1, o);
    d2 += __shfl_down_sync(0xffffffffu, d2, o);
  }
  if (col == 0){ sred[rb_] = d1; sred2[rb_] = d2; }
  __syncthreads();
  if (threadIdx.x == 0){
    float s1 = 0.f, s2 = 0.f;
    #pragma unroll
    for (int i = 0; i < 8; i++){ s1 += sred[i]; s2 += sred2[i]; }
    atomicAdd(&g_scal[GAM+0], s1);
    atomicAdd(&g_scal[BBIDX], s2);
  }
}

__global__ void finalize_kernel(){
  if (threadIdx.x == 0) g_scal[ATOL2] = 1e-12f * g_scal[BBIDX];
}

// ---------------- init2: w0 = A r0, reduce delta0 = <r0,w0> ----------------
__global__ void __launch_bounds__(256) cg_init2_kernel(
    const float* __restrict__ R0, float* __restrict__ W0,
    const float* __restrict__ mask, const float* __restrict__ loglam)
{
  const float lam = expf(loglam[0]);
  __shared__ float sp[34][36];
  const int b = blockIdx.z;
  const int tx0 = blockIdx.x*32, ty0 = blockIdx.y*32;
  const float* vb = R0 + (size_t)b*HW;
  for (int idx = threadIdx.x; idx < 34*34; idx += 256){
    int yy = idx/34, xx = idx - yy*34;
    int gy = ty0+yy-1, gx = tx0+xx-1;
    float v = 0.f;
    if (gy >= 0 && gy < HP && gx >= 0 && gx < HP) v = vb[gy*HP+gx];
    sp[yy][xx] = v;
  }
  matvec_phase2(sp, lam, mask, b, tx0, ty0, W0 + (size_t)b*HW, -1, DEL+0);
}

// ---------------- Chronopoulos–Gear single-kernel CG iteration ----------------
// beta_k = gamma_k/gamma_{k-1} (0 @k=0); alpha_k = gamma_k/(delta_k - beta_k*gamma_k/alpha_{k-1})
// tile+halo (stable inputs): s_k = w_k + beta*s_{k-1}; r_{k+1} = r_k - alpha*s_k
// interior: p_k = r_k + beta*p_{k-1}; x += alpha*p_k; write s,r,p,x.
// then w_{k+1} = A r_{k+1} from smem; reduce gamma_{k+1}, delta_{k+1}.
__global__ void __launch_bounds__(256) cgcg_iter_kernel(
    const float* __restrict__ R_in, const float* __restrict__ W_in, const float* __restrict__ S_in,
    float* __restrict__ R_out, float* __restrict__ W_out, float* __restrict__ S_out,
    float* __restrict__ P, float* __restrict__ X,
    const float* __restrict__ mask, int k, const float* __restrict__ loglam)
{
  float gam = g_scal[GAM+k];
  if (!(gam > g_scal[ATOL2])) return;
  float beta, alpha;
  if (k == 0){
    beta = 0.f; alpha = gam / g_scal[DEL+0];
  } else {
    beta = gam / g_scal[GAM+k-1];
    alpha = gam / (g_scal[DEL+k] - beta*gam/g_scal[ALF+k-1]);
  }
  if (threadIdx.x == 0) g_scal[ALF+k] = alpha;   // same value from all blocks

  const float lam = expf(loglam[0]);
  __shared__ float sp[34][36];
  const int b = blockIdx.z;
  const int tx0 = blockIdx.x*32, ty0 = blockIdx.y*32;
  const size_t boff = (size_t)b*HW;
  const float *Ri = R_in + boff, *Wi = W_in + boff, *Si = S_in + boff;
  float *Ro = R_out + boff, *So = S_out + boff, *Pp = P + boff, *Xp = X + boff;

  for (int idx = threadIdx.x; idx < 34*34; idx += 256){
    int yy = idx/34, xx = idx - yy*34;
    int gy = ty0+yy-1, gx = tx0+xx-1;
    float rn = 0.f;
    if (gy >= 0 && gy < HP && gx >= 0 && gx < HP){
      int o = gy*HP+gx;
      float rr = Ri[o];
      float s  = (k == 0) ? Wi[o] : fmaf(beta, Si[o], Wi[o]);
      rn = fmaf(-alpha, s, rr);
      if (yy >= 1 && yy <= 32 && xx >= 1 && xx <= 32){
        So[o] = s; Ro[o] = rn;
        float pn = (k == 0) ? rr : fmaf(beta, Pp[o], rr);
        Pp[o] = pn;
        Xp[o] = fmaf(alpha, pn, Xp[o]);
      }
    }
    sp[yy][xx] = rn;
  }
  matvec_phase2(sp, lam, mask, b, tx0, ty0, W_out + boff, GAM+k+1, DEL+k+1);
}

// ---------------- host orchestration ----------------
extern "C" void kernel_launch(void* const* d_in, const int* in_sizes, int n_in,
                              void* d_out, int out_size)
{
  const float* guide  = (const float*)d_in[0];
  const float* source = (const float*)d_in[1];
  const float* mask   = (const float*)d_in[2];
  const float* ybic   = (const float*)d_in[3];
  const float* gw1 = (const float*)d_in[4];  const float* gb1 = (const float*)d_in[5];
  const float* gw2 = (const float*)d_in[6];  const float* gb2 = (const float*)d_in[7];
  const float* sw1 = (const float*)d_in[8];  const float* sb1 = (const float*)d_in[9];
  const float* sw2 = (const float*)d_in[10]; const float* sb2 = (const float*)d_in[11];
  const float* vw1 = (const float*)d_in[12]; const float* vb1 = (const float*)d_in[13];
  const float* vw2 = (const float*)d_in[14]; const float* vb2 = (const float*)d_in[15];
  const float* vw3 = (const float*)d_in[16]; const float* vb3 = (const float*)d_in[17];
  const float* loglam = (const float*)d_in[18];
  const float* logmu  = (const float*)d_in[19];

  float* out  = (float*)d_out;
  float* xout = out;
  float* var  = out + (size_t)NTOT;
  float* aff  = out + (size_t)2*NTOT;

  float *h1p, *h2p, *h3p;
  float *r0p, *r1p, *s0p, *s1p, *w0p, *w1p, *pp;
  cudaGetSymbolAddress((void**)&h1p, g_h1);
  cudaGetSymbolAddress((void**)&h2p, g_h2);
  cudaGetSymbolAddress((void**)&h3p, g_h3);
  cudaGetSymbolAddress((void**)&r0p, g_R0);
  cudaGetSymbolAddress((void**)&r1p, g_R1);
  cudaGetSymbolAddress((void**)&s0p, g_S0);
  cudaGetSymbolAddress((void**)&s1p, g_S1);
  cudaGetSymbolAddress((void**)&w0p, g_W0);
  cudaGetSymbolAddress((void**)&w1p, g_W1);
  cudaGetSymbolAddress((void**)&pp , g_P );

  dim3 gc(16, 16, NB);
  dim3 g1(8, 8, NB);
  dim3 gm(8, 8, NB);

  zero_scal_kernel<<<1,256>>>();

  // variance net: concat(guide, ybic) -> 32 -> 32 -> 1
  conv3x3_pair<3,1,32,true ><<<gc,256>>>(guide, ybic, vw1, vb1, h1p);
  conv3x3_pair<32,0,32,true ><<<gc,256>>>(h1p, nullptr, vw2, vb2, h2p);
  conv3x3_one<<<g1,256>>>(h2p, vw3, vb3, var);

  // guide features: guide -> 32 -> 32
  conv3x3_pair<3,0,32,true ><<<gc,256>>>(guide, nullptr, gw1, gb1, h1p);
  conv3x3_pair<32,0,32,false><<<gc,256>>>(h1p, nullptr, gw2, gb2, h2p);

  // source features: ybic -> 32 -> 32
  conv3x3_pair<1,0,32,true ><<<gc,256>>>(ybic, nullptr, sw1, sb1, h1p);
  conv3x3_pair<32,0,32,false><<<gc,256>>>(h1p, nullptr, sw2, sb2, h3p);

  // edge weights + aff output
  affinity_kernel<<<NTOT/256,256>>>(logmu);
  assemble_kernel<<<NTOT/256,256>>>(aff, loglam);

  // CG init
  cg_init_kernel<<<gm,256>>>(ybic, source, mask, xout, r0p, loglam);
  finalize_kernel<<<1,32>>>();
  cg_init2_kernel<<<gm,256>>>(r0p, w0p, mask, loglam);

  // single-kernel CG-CG iterations (ping-pong R/W/S)
  for (int k = 0; k < 100; k++){
    if ((k & 1) == 0)
      cgcg_iter_kernel<<<gm,256>>>(r0p, w0p, s0p, r1p, w1p, s1p, pp, xout, mask, k, loglam);
    else
      cgcg_iter_kernel<<<gm,256>>>(r1p, w1p, s1p, r0p, w0p, s0p, pp, xout, mask, k, loglam);
  }
}